// round 4
// baseline (speedup 1.0000x reference)
#include <cuda_runtime.h>
#include <cuda_bf16.h>
#include <cstdint>

#define MSL 256
#define EMB 1024
#define NHID 64
#define NSLAB 4
#define DSLAB (EMB / NSLAB)   // 256
#define NEGF (-1e20f)

// Transposed scratch for coalesced reduction: [in/mem][slab][k][pos]
__device__ float g_part[2][NSLAB][NHID][MSL];
// Reduced + ReLU'd hidden vectors. [in/mem][k]
__device__ float g_h[2][NHID];

// ---------------------------------------------------------------------------
// Kernel A: fused dual GEMV over w1, K-split, software-pipelined loads.
// grid = 1024 (pos = b>>2, slab = b&3), block = 256 threads, <=64 regs.
// Each block streams a contiguous 64KB slab of w1 once. Per thread: 16
// float4 loads in 4 batches of 4, double-buffered -> up to 8 LDG.128 in
// flight per thread for latency hiding.
// ---------------------------------------------------------------------------
__global__ __launch_bounds__(256, 4) void gemv_kernel(
    const int* __restrict__ toks_in, int n_toks,
    const int* __restrict__ toks_mem,
    const float* __restrict__ emb,
    const float* __restrict__ w1)
{
    __shared__ float s_in[DSLAB];
    __shared__ float s_mem[DSLAB];
    __shared__ float red_in[16][NHID];
    __shared__ float red_mem[16][NHID];

    const int pos    = blockIdx.x >> 2;
    const int slab   = blockIdx.x & 3;
    const int d_base = slab * DSLAB;
    const int t      = threadIdx.x;

    const int tok_in  = (pos < n_toks) ? toks_in[pos] : 0;  // PAD = 0
    const int tok_mem = toks_mem[pos];

    // Stage the two 1KB embedding slab segments into SMEM.
    if (t < 64) {
        ((float4*)s_in)[t] =
            ((const float4*)(emb + (size_t)tok_in * EMB + d_base))[t];
    } else if (t < 128) {
        ((float4*)s_mem)[t - 64] =
            ((const float4*)(emb + (size_t)tok_mem * EMB + d_base))[t - 64];
    }

    const float4* wp =
        (const float4*)(w1 + ((size_t)pos * EMB + d_base) * NHID) + t;
    const int j_off = t >> 4;          // 0..15  (d stripe)
    const int k0    = (t & 15) * 4;    // 0,4,...,60

    // Issue first load batch BEFORE the barrier (independent of SMEM writes).
    float4 a0 = wp[0 * 256], a1 = wp[1 * 256],
           a2 = wp[2 * 256], a3 = wp[3 * 256];
    __syncthreads();

    float4 ai = make_float4(0.f, 0.f, 0.f, 0.f);
    float4 am = make_float4(0.f, 0.f, 0.f, 0.f);

    #pragma unroll
    for (int m = 0; m < 16; m += 4) {
        float4 b0, b1, b2, b3;
        if (m + 4 < 16) {
            const float4* q = wp + (m + 4) * 256;
            b0 = q[0 * 256]; b1 = q[1 * 256];
            b2 = q[2 * 256]; b3 = q[3 * 256];
        }
        #pragma unroll
        for (int u = 0; u < 4; ++u) {
            float4 w = (u == 0) ? a0 : (u == 1) ? a1 : (u == 2) ? a2 : a3;
            int   d  = (m + u) * 16 + j_off;
            float a  = s_in[d];
            float b  = s_mem[d];
            ai.x += a * w.x; ai.y += a * w.y; ai.z += a * w.z; ai.w += a * w.w;
            am.x += b * w.x; am.y += b * w.y; am.z += b * w.z; am.w += b * w.w;
        }
        a0 = b0; a1 = b1; a2 = b2; a3 = b3;
    }

    red_in [j_off][k0 + 0] = ai.x;
    red_in [j_off][k0 + 1] = ai.y;
    red_in [j_off][k0 + 2] = ai.z;
    red_in [j_off][k0 + 3] = ai.w;
    red_mem[j_off][k0 + 0] = am.x;
    red_mem[j_off][k0 + 1] = am.y;
    red_mem[j_off][k0 + 2] = am.z;
    red_mem[j_off][k0 + 3] = am.w;
    __syncthreads();

    if (t < NHID) {
        float si = 0.f, sm = 0.f;
        #pragma unroll
        for (int r = 0; r < 16; ++r) {
            si += red_in [r][t];
            sm += red_mem[r][t];
        }
        g_part[0][slab][t][pos] = si;
        g_part[1][slab][t][pos] = sm;
    }
}

// ---------------------------------------------------------------------------
// Kernel B: reduce g_part over (slab, pos) -> +b1 -> ReLU -> g_h.
// grid = 128 (one block per (s,k)), block = 256 (one thread per pos).
// ---------------------------------------------------------------------------
__global__ __launch_bounds__(256) void reduce_kernel(
    const float* __restrict__ b1)
{
    __shared__ float warp_sums[8];
    const int s = blockIdx.x >> 6;     // 0..1
    const int k = blockIdx.x & 63;     // 0..63
    const int t = threadIdx.x;

    float v = g_part[s][0][k][t] + g_part[s][1][k][t]
            + g_part[s][2][k][t] + g_part[s][3][k][t];

    #pragma unroll
    for (int off = 16; off > 0; off >>= 1)
        v += __shfl_down_sync(0xffffffffu, v, off);
    if ((t & 31) == 0) warp_sums[t >> 5] = v;
    __syncthreads();
    if (t == 0) {
        float sum = 0.f;
        #pragma unroll
        for (int w = 0; w < 8; ++w) sum += warp_sums[w];
        g_h[s][k] = fmaxf(sum + b1[k], 0.f);
    }
}

// ---------------------------------------------------------------------------
// Bitonic sort of 512 u64 keys in shared memory, 256 threads, ascending.
// j <= 32 stages stay inside warp-private 64-element segments -> __syncwarp.
// ---------------------------------------------------------------------------
__device__ __forceinline__ void bitonic_sort_512(unsigned long long* keys)
{
    const int t = threadIdx.x;
    bool prev_cross = true;
    for (int k = 2; k <= 512; k <<= 1) {
        for (int j = k >> 1; j > 0; j >>= 1) {
            const bool cross = (j >= 64);
            if (cross || prev_cross) __syncthreads();
            else                     __syncwarp();
            prev_cross = cross;
            int i   = ((t & ~(j - 1)) << 1) | (t & (j - 1));
            int ixj = i | j;
            unsigned long long a = keys[i];
            unsigned long long b = keys[ixj];
            bool up = ((i & k) == 0);
            if ((a > b) == up) { keys[i] = b; keys[ixj] = a; }
        }
    }
    __syncthreads();
}

// ---------------------------------------------------------------------------
// Kernel C: layer2 + sigmoid -> mask PAD -> scatter-max dedup + top-k via
// two bitonic sorts -> emit. 1 block, 256 threads.
// ---------------------------------------------------------------------------
__global__ __launch_bounds__(256) void final_kernel(
    const int* __restrict__ toks_in, int n_toks,
    const int* __restrict__ toks_mem,
    const float* __restrict__ w2,
    const float* __restrict__ b2,
    float* __restrict__ out)
{
    __shared__ float h_in[NHID];
    __shared__ float h_mem[NHID];
    __shared__ unsigned long long keys[512];

    const int t = threadIdx.x;

    // Kick off token loads early (used after the GEMV loop).
    int tok_a = (t < n_toks) ? toks_in[t] : 0;
    int tok_b = toks_mem[t];

    if (t < NHID)        h_in [t]        = g_h[0][t];
    else if (t < 2*NHID) h_mem[t - NHID] = g_h[1][t - NHID];
    __syncthreads();

    // ---- layer 2 + sigmoid (w2 column shared by both score vectors) ----
    float si, sm;
    {
        si = b2[t];
        sm = si;
        #pragma unroll 16
        for (int k = 0; k < NHID; ++k) {
            float w = w2[k * MSL + t];   // coalesced over t
            si += h_in[k]  * w;
            sm += h_mem[k] * w;
        }
        si = 1.f / (1.f + expf(-si));
        sm = 1.f / (1.f + expf(-sm));
    }

    // ---- build keys (token asc, score desc); PAD -> sentinel ----
    {
        unsigned sb_a = __float_as_uint(si);   // positive floats: bits monotonic
        unsigned sb_b = __float_as_uint(sm);
        keys[t] = (tok_a == 0) ? ~0ull
                 : (((unsigned long long)(unsigned)tok_a << 32) | (unsigned)(~sb_a));
        keys[t + 256] = (tok_b == 0) ? ~0ull
                 : (((unsigned long long)(unsigned)tok_b << 32) | (unsigned)(~sb_b));
    }

    // Sort1: groups duplicates; best score first within each token group.
    bitonic_sort_512(keys);

    // ---- dedup (scatter-max): winner = first entry of its token ----
    unsigned long long k_a = keys[t];
    unsigned long long k_b = keys[t + 256];
    unsigned long long p_a = (t == 0) ? ~0ull : keys[t - 1];
    unsigned long long p_b = keys[t + 255];
    bool win_a = (k_a != ~0ull) && (t == 0 || (k_a >> 32) != (p_a >> 32));
    bool win_b = (k_b != ~0ull) && ((k_b >> 32) != (p_b >> 32));
    __syncthreads();

    // key2 = swap halves: (~score_bits)<<32 | token -> asc = score desc, tok asc
    keys[t]       = win_a ? ((k_a << 32) | (k_a >> 32)) : ~0ull;
    keys[t + 256] = win_b ? ((k_b << 32) | (k_b >> 32)) : ~0ull;

    // Sort2: top-k order.
    bitonic_sort_512(keys);

    // ---- emit first 256 (tokens as float, then scores) ----
    {
        unsigned long long r = keys[t];
        bool present = (r != ~0ull);
        unsigned tok = (unsigned)r;                       // low 32
        float score  = __uint_as_float(~(unsigned)(r >> 32));
        out[t]       = present ? (float)tok : 0.0f;
        out[MSL + t] = present ? score : NEGF;
    }
}

extern "C" void kernel_launch(void* const* d_in, const int* in_sizes, int n_in,
                              void* d_out, int out_size)
{
    const int*   toks_in  = (const int*)  d_in[0];
    const int*   toks_mem = (const int*)  d_in[1];
    const float* emb      = (const float*)d_in[2];
    const float* w1       = (const float*)d_in[3];
    const float* b1       = (const float*)d_in[4];
    const float* w2       = (const float*)d_in[5];
    const float* b2       = (const float*)d_in[6];
    const int n_toks = in_sizes[0];

    gemv_kernel<<<MSL * NSLAB, 256>>>(toks_in, n_toks, toks_mem, emb, w1);
    reduce_kernel<<<128, 256>>>(b1);
    final_kernel<<<1, 256>>>(toks_in, n_toks, toks_mem, w2, b2, (float*)d_out);
}